// round 15
// baseline (speedup 1.0000x reference)
#include <cuda_runtime.h>
#include <cuda_fp16.h>
#include <math.h>
#include <stdint.h>

// Problem constants
#define B 4096
#define K 128
#define C 100
#define MARGIN 0.3f

#define PW_BLOCKS ((32 * 33) / 2)   // 528 triangular 128x128 tiles
#define CE_ROWS 16
#define CE_BLOCKS (B / CE_ROWS)     // 256

#define TS 136                      // padded k-stride (fp16 units)
#define PW_SMEM (2 * 128 * TS * 2)  // Ahi/Bhi = 69632 B (2 CTAs/SM)

typedef unsigned long long u64;

// Scratch (device globals). maxbits/minbits/rdone are memset-initialized:
// 0x00000000 = 0.0f; 0x7f7f7f7f = 3.39e38f (> any real d^2).
__device__ int      g_maxbits[B];
__device__ int      g_minbits[B];
__device__ float    g_ce[B];
__device__ float    g_part_tr[16];
__device__ float    g_part_ce[16];
__device__ unsigned g_rdone;

// ---------------------------------------------------------------------------
// HMMA helpers (fp16)
// ---------------------------------------------------------------------------
__device__ __forceinline__ uint32_t lds_u32(const __half* t, int row, int col) {
    return *reinterpret_cast<const uint32_t*>(t + row * TS + col);
}

__device__ __forceinline__ void mma16816(float* d,
                                         uint32_t a0, uint32_t a1, uint32_t a2, uint32_t a3,
                                         uint32_t b0, uint32_t b1) {
    asm volatile(
        "mma.sync.aligned.m16n8k16.row.col.f32.f16.f16.f32 "
        "{%0,%1,%2,%3}, {%4,%5,%6,%7}, {%8,%9}, {%0,%1,%2,%3};"
        : "+f"(d[0]), "+f"(d[1]), "+f"(d[2]), "+f"(d[3])
        : "r"(a0), "r"(a1), "r"(a2), "r"(a3), "r"(b0), "r"(b1));
}

__device__ __forceinline__ void store_hi(__half* hi, int row, int c4, float4 v) {
    __half2 hp01 = __halves2half2(__float2half_rn(v.x), __float2half_rn(v.y));
    __half2 hp23 = __halves2half2(__float2half_rn(v.z), __float2half_rn(v.w));
    uint2 hp;
    hp.x = *reinterpret_cast<uint32_t*>(&hp01);
    hp.y = *reinterpret_cast<uint32_t*>(&hp23);
    *reinterpret_cast<uint2*>(hi + row * TS + c4 * 4) = hp;
}

// Row norm from fp16 smem tile (reads 128 halfs = 16 uint4).
__device__ __forceinline__ float tile_row_norm(const __half* t, int row) {
    const uint4* rp = reinterpret_cast<const uint4*>(t + row * TS);
    float s = 0.0f;
    #pragma unroll
    for (int i = 0; i < 16; i++) {
        uint4 q = rp[i];
        const __half2* h = reinterpret_cast<const __half2*>(&q);
        #pragma unroll
        for (int j = 0; j < 4; j++) {
            float2 f = __half22float2(h[j]);
            s += f.x * f.x + f.y * f.y;
        }
    }
    return s;
}

// ---------------------------------------------------------------------------
// Pairwise body: single-pass fp16 Gram via mma.sync + fused triplet epilogue.
// Norms computed in-block from the fp16 tiles => d2 = ||a_h - b_h||^2 exactly
// (consistent rounding). No prep kernel needed.
// ---------------------------------------------------------------------------
__device__ __forceinline__ void pairwise_body(char* smraw, const float* __restrict__ emb,
                                              const int* __restrict__ labels, int bid) {
    __half* Ahi = reinterpret_cast<__half*>(smraw);
    __half* Bhi = Ahi + 128 * TS;
    __shared__ int   labA[128], labB[128];
    __shared__ float sqA[128], sqB[128];
    __shared__ float s_cp[8][128], s_cn[8][128];

    // Triangular block decode: by <= bx
    float tf = sqrtf(8.0f * (float)bid + 1.0f);
    int bx = (int)((tf - 1.0f) * 0.5f);
    while ((bx + 1) * (bx + 2) / 2 <= bid) bx++;
    while (bx * (bx + 1) / 2 > bid) bx--;
    int by = bid - bx * (bx + 1) / 2;
    const bool diag = (by == bx);

    const int tid  = threadIdx.x;
    const int wid  = tid >> 5;
    const int lane = tid & 31;
    const int g    = lane >> 2;      // fragment group 0-7
    const int t    = lane & 3;       // thread-in-group 0-3
    const int i0   = by * 128;
    const int j0   = bx * 128;

    const float4* e4 = reinterpret_cast<const float4*>(emb);
    #pragma unroll
    for (int f = tid; f < 128 * 32; f += 256) {
        int row = f >> 5, c4 = f & 31;
        store_hi(Ahi, row, c4, e4[(i0 + row) * 32 + c4]);
        store_hi(Bhi, row, c4, e4[(j0 + row) * 32 + c4]);
    }
    if (tid < 128) {
        labA[tid] = labels[i0 + tid];
        labB[tid] = labels[j0 + tid];
    }
    __syncthreads();

    // Row norms from the fp16 tiles (threads 0-127: A rows; 128-255: B rows).
    {
        int row = tid & 127;
        if (tid < 128) sqA[row] = tile_row_norm(Ahi, row);
        else           sqB[row] = tile_row_norm(Bhi, row);
    }
    __syncthreads();

    float d[16][4];
    #pragma unroll
    for (int nb = 0; nb < 16; nb++)
        #pragma unroll
        for (int e = 0; e < 4; e++) d[nb][e] = 0.0f;

    const int r0 = wid * 16;

    #pragma unroll 2
    for (int s = 0; s < 8; s++) {
        int k0 = 16 * s;
        uint32_t a0 = lds_u32(Ahi, r0 + g,     k0 + 2 * t);
        uint32_t a1 = lds_u32(Ahi, r0 + g + 8, k0 + 2 * t);
        uint32_t a2 = lds_u32(Ahi, r0 + g,     k0 + 8 + 2 * t);
        uint32_t a3 = lds_u32(Ahi, r0 + g + 8, k0 + 8 + 2 * t);
        #pragma unroll
        for (int nb = 0; nb < 16; nb++) {
            uint32_t b0 = lds_u32(Bhi, 8 * nb + g, k0 + 2 * t);
            uint32_t b1 = lds_u32(Bhi, 8 * nb + g, k0 + 8 + 2 * t);
            mma16816(d[nb], a0, a1, a2, a3, b0, b1);
        }
    }

    // Epilogue on fragment layout: thread (g,t) holds rows {r0+g, r0+g+8},
    // cols {8nb+2t, 8nb+2t+1}.
    const float INF = __int_as_float(0x7f800000);
    int   la0 = labA[r0 + g], la1 = labA[r0 + g + 8];
    float si0 = sqA[r0 + g],  si1 = sqA[r0 + g + 8];
    float rp0 = 0.0f, rn0 = INF, rp1 = 0.0f, rn1 = INF;

    #pragma unroll
    for (int nb = 0; nb < 16; nb++) {
        int   jc  = 8 * nb + 2 * t;
        int   lj0 = labB[jc], lj1 = labB[jc + 1];
        float sj0 = sqB[jc],  sj1 = sqB[jc + 1];
        float e00 = fmaxf(si0 + sj0 - 2.0f * d[nb][0], 0.0f);
        float e01 = fmaxf(si0 + sj1 - 2.0f * d[nb][1], 0.0f);
        float e10 = fmaxf(si1 + sj0 - 2.0f * d[nb][2], 0.0f);
        float e11 = fmaxf(si1 + sj1 - 2.0f * d[nb][3], 0.0f);

        // Row-side
        if (lj0 == la0) rp0 = fmaxf(rp0, e00); else rn0 = fminf(rn0, e00);
        if (lj1 == la0) rp0 = fmaxf(rp0, e01); else rn0 = fminf(rn0, e01);
        if (lj0 == la1) rp1 = fmaxf(rp1, e10); else rn1 = fminf(rn1, e10);
        if (lj1 == la1) rp1 = fmaxf(rp1, e11); else rn1 = fminf(rn1, e11);

        // Col-side (off-diagonal blocks only)
        if (!diag) {
            float cp0 = 0.0f, cn0 = INF, cp1 = 0.0f, cn1 = INF;
            if (lj0 == la0) cp0 = e00;             else cn0 = e00;
            if (lj0 == la1) cp0 = fmaxf(cp0, e10); else cn0 = fminf(cn0, e10);
            if (lj1 == la0) cp1 = e01;             else cn1 = e01;
            if (lj1 == la1) cp1 = fmaxf(cp1, e11); else cn1 = fminf(cn1, e11);
            #pragma unroll
            for (int m = 4; m <= 16; m <<= 1) {
                cp0 = fmaxf(cp0, __shfl_xor_sync(0xffffffffu, cp0, m));
                cn0 = fminf(cn0, __shfl_xor_sync(0xffffffffu, cn0, m));
                cp1 = fmaxf(cp1, __shfl_xor_sync(0xffffffffu, cp1, m));
                cn1 = fminf(cn1, __shfl_xor_sync(0xffffffffu, cn1, m));
            }
            if (g == 0) {
                s_cp[wid][jc]     = cp0;
                s_cp[wid][jc + 1] = cp1;
                s_cn[wid][jc]     = cn0;
                s_cn[wid][jc + 1] = cn1;
            }
        }
    }

    // Row combine across t + atomics
    #pragma unroll
    for (int m = 1; m <= 2; m <<= 1) {
        rp0 = fmaxf(rp0, __shfl_xor_sync(0xffffffffu, rp0, m));
        rn0 = fminf(rn0, __shfl_xor_sync(0xffffffffu, rn0, m));
        rp1 = fmaxf(rp1, __shfl_xor_sync(0xffffffffu, rp1, m));
        rn1 = fminf(rn1, __shfl_xor_sync(0xffffffffu, rn1, m));
    }
    if (t == 0) {
        atomicMax(&g_maxbits[i0 + r0 + g],     __float_as_int(rp0));
        atomicMin(&g_minbits[i0 + r0 + g],     __float_as_int(rn0));
        atomicMax(&g_maxbits[i0 + r0 + g + 8], __float_as_int(rp1));
        atomicMin(&g_minbits[i0 + r0 + g + 8], __float_as_int(rn1));
    }

    if (!diag) {
        __syncthreads();
        if (tid < 128) {
            float p = s_cp[0][tid], n = s_cn[0][tid];
            #pragma unroll
            for (int w = 1; w < 8; w++) {
                p = fmaxf(p, s_cp[w][tid]);
                n = fminf(n, s_cn[w][tid]);
            }
            atomicMax(&g_maxbits[j0 + tid], __float_as_int(p));
            atomicMin(&g_minbits[j0 + tid], __float_as_int(n));
        }
    }
}

// ---------------------------------------------------------------------------
// CE body (R6 version; labels read directly from input).
// ---------------------------------------------------------------------------
__device__ __forceinline__ void ce_body(float* sm, const float* __restrict__ emb,
                                        const int* __restrict__ labels,
                                        const float* __restrict__ w,
                                        const float* __restrict__ bias, int bid) {
    float* w_s = sm;                        // [100][133]
    float* e_s = sm + C * 133;              // [16][129]
    float* lg  = e_s + CE_ROWS * 129;       // [16][100]

    int tid = threadIdx.x;
    int r0  = bid * CE_ROWS;

    for (int f = tid; f < C * K; f += 256) {
        int c = f >> 7, k = f & 127;
        w_s[c * 133 + k] = w[f];
    }
    for (int f = tid; f < CE_ROWS * K; f += 256) {
        int r = f >> 7, k = f & 127;
        e_s[r * 129 + k] = emb[(r0 + r) * K + k];
    }
    __syncthreads();

    int grp = tid >> 7;
    int c   = tid & 127;
    if (c < C) {
        float accv[8];
        float bv = bias[c];
        #pragma unroll
        for (int r = 0; r < 8; r++) accv[r] = bv;
        for (int k = 0; k < K; k++) {
            float wv = w_s[c * 133 + k];
            #pragma unroll
            for (int r = 0; r < 8; r++)
                accv[r] = fmaf(wv, e_s[(grp * 8 + r) * 129 + k], accv[r]);
        }
        #pragma unroll
        for (int r = 0; r < 8; r++) lg[(grp * 8 + r) * C + c] = accv[r];
    }
    __syncthreads();

    if (tid < CE_ROWS) {
        int   lab = labels[r0 + tid];
        float m = -1e30f;
        for (int cc = 0; cc < C; cc++) m = fmaxf(m, lg[tid * C + cc]);
        float s = 0.0f;
        for (int cc = 0; cc < C; cc++) s += expf(lg[tid * C + cc] - m);
        g_ce[r0 + tid] = m + logf(s) - lg[tid * C + lab];
    }
}

// Fused kernel — no tail; 2 CTAs/SM for phase overlap.
__global__ void __launch_bounds__(256, 2)
fused_kernel(const float* __restrict__ emb, const int* __restrict__ labels,
             const float* __restrict__ w, const float* __restrict__ bias) {
    extern __shared__ char smraw[];
    if (blockIdx.x < PW_BLOCKS)
        pairwise_body(smraw, emb, labels, blockIdx.x);
    else
        ce_body(reinterpret_cast<float*>(smraw), emb, labels, w, bias,
                blockIdx.x - PW_BLOCKS);
}

// ---------------------------------------------------------------------------
// Single reduce kernel (R9 version).
// ---------------------------------------------------------------------------
__global__ void reduce_kernel(float* __restrict__ out) {
    __shared__ float    s1[256], s2[256];
    __shared__ unsigned s_last;
    int t = threadIdx.x;
    int i = blockIdx.x * 256 + t;
    float mx = fmaxf(__int_as_float(g_maxbits[i]), 1e-12f);
    float mn = fmaxf(__int_as_float(g_minbits[i]), 1e-12f);
    s1[t] = fmaxf(sqrtf(mx) - sqrtf(mn) + MARGIN, 0.0f);
    s2[t] = g_ce[i];
    __syncthreads();
    #pragma unroll
    for (int s = 128; s > 0; s >>= 1) {
        if (t < s) { s1[t] += s1[t + s]; s2[t] += s2[t + s]; }
        __syncthreads();
    }
    if (t == 0) {
        g_part_tr[blockIdx.x] = s1[0];
        g_part_ce[blockIdx.x] = s2[0];
        __threadfence();
        s_last = (atomicAdd(&g_rdone, 1u) == 15u) ? 1u : 0u;
    }
    __syncthreads();
    if (s_last && t < 32) {
        float v = 0.0f;
        if (t < 16) v = __ldcg(&g_part_tr[t]) + __ldcg(&g_part_ce[t]);
        #pragma unroll
        for (int m = 8; m; m >>= 1) v += __shfl_xor_sync(0xffffffffu, v, m);
        if (t == 0) out[0] = v * (1.0f / (float)B);
    }
}

// ---------------------------------------------------------------------------
extern "C" void kernel_launch(void* const* d_in, const int* in_sizes, int n_in,
                              void* d_out, int out_size) {
    const float* emb    = (const float*)d_in[0];
    const int*   labels = (const int*)d_in[1];
    const float* fcw    = (const float*)d_in[2];
    const float* fcb    = (const float*)d_in[3];
    float*       out    = (float*)d_out;

    cudaFuncSetAttribute(fused_kernel,
                         cudaFuncAttributeMaxDynamicSharedMemorySize, PW_SMEM);

    void *p_max, *p_min, *p_rdone;
    cudaGetSymbolAddress(&p_max,   g_maxbits);
    cudaGetSymbolAddress(&p_min,   g_minbits);
    cudaGetSymbolAddress(&p_rdone, g_rdone);

    cudaMemsetAsync(p_max,   0x00, B * sizeof(int));   // 0.0f
    cudaMemsetAsync(p_min,   0x7f, B * sizeof(int));   // 3.39e38f (acts as +inf)
    cudaMemsetAsync(p_rdone, 0x00, sizeof(unsigned));

    fused_kernel<<<PW_BLOCKS + CE_BLOCKS, 256, PW_SMEM>>>(emb, labels, fcw, fcb);
    reduce_kernel<<<16, 256>>>(out);
}

// round 16
// speedup vs baseline: 1.1623x; 1.1623x over previous
#include <cuda_runtime.h>
#include <cuda_fp16.h>
#include <math.h>
#include <stdint.h>

// Problem constants
#define B 4096
#define K 128
#define C 100
#define MARGIN 0.3f

#define PW_BLOCKS ((32 * 33) / 2)   // 528 triangular 128x128 tiles
#define CE_ROWS 16
#define CE_BLOCKS (B / CE_ROWS)     // 256

#define TS 136                      // padded k-stride (fp16 units)
#define PW_SMEM (2 * 128 * TS * 2)  // Ahi/Bhi = 69632 B (2 CTAs/SM)

typedef unsigned long long u64;

// Scratch (device globals)
__device__ int      g_maxbits[B];
__device__ int      g_minbits[B];
__device__ float    g_sq[B];
__device__ float    g_ce[B];
__device__ int      g_lab[B];
__device__ __half   g_embh[B * K];    // fp16-staged embeddings
__device__ float    g_part_tr[16];
__device__ float    g_part_ce[16];
__device__ unsigned g_rdone;

// ---------------------------------------------------------------------------
// Kernel 1: squared norms + init + labels + fp16 staging (MLP-batched).
// ---------------------------------------------------------------------------
__global__ void prep_kernel(const float* __restrict__ emb,
                            const int* __restrict__ labels) {
    int warp = (blockIdx.x * blockDim.x + threadIdx.x) >> 5;
    int lane = threadIdx.x & 31;
    int base = warp * 8;

    const float4* e4 = reinterpret_cast<const float4*>(emb);
    float4 v[8];
    #pragma unroll
    for (int k = 0; k < 8; k++) v[k] = e4[(base + k) * 32 + lane];

    float s[8];
    #pragma unroll
    for (int k = 0; k < 8; k++) {
        s[k] = v[k].x * v[k].x + v[k].y * v[k].y + v[k].z * v[k].z + v[k].w * v[k].w;
        // fp16 staging: 4 floats -> 2x half2 -> uint2
        __half2 h01 = __halves2half2(__float2half_rn(v[k].x), __float2half_rn(v[k].y));
        __half2 h23 = __halves2half2(__float2half_rn(v[k].z), __float2half_rn(v[k].w));
        uint2 hp;
        hp.x = *reinterpret_cast<uint32_t*>(&h01);
        hp.y = *reinterpret_cast<uint32_t*>(&h23);
        *reinterpret_cast<uint2*>(&g_embh[(base + k) * K + lane * 4]) = hp;
    }

    #pragma unroll
    for (int m = 16; m; m >>= 1)
        #pragma unroll
        for (int k = 0; k < 8; k++)
            s[k] += __shfl_xor_sync(0xffffffffu, s[k], m);

    if (lane < 8) {
        int row = base + lane;
        g_sq[row]      = s[lane];
        g_maxbits[row] = 0;
        g_minbits[row] = 0x7f800000;
        g_lab[row]     = labels[row];
    }
}

// ---------------------------------------------------------------------------
// HMMA helpers (fp16)
// ---------------------------------------------------------------------------
__device__ __forceinline__ uint32_t lds_u32(const __half* t, int row, int col) {
    return *reinterpret_cast<const uint32_t*>(t + row * TS + col);
}

__device__ __forceinline__ void mma16816(float* d,
                                         uint32_t a0, uint32_t a1, uint32_t a2, uint32_t a3,
                                         uint32_t b0, uint32_t b1) {
    asm volatile(
        "mma.sync.aligned.m16n8k16.row.col.f32.f16.f16.f32 "
        "{%0,%1,%2,%3}, {%4,%5,%6,%7}, {%8,%9}, {%0,%1,%2,%3};"
        : "+f"(d[0]), "+f"(d[1]), "+f"(d[2]), "+f"(d[3])
        : "r"(a0), "r"(a1), "r"(a2), "r"(a3), "r"(b0), "r"(b1));
}

// ---------------------------------------------------------------------------
// Pairwise body: single-pass fp16 Gram via mma.sync + fused triplet epilogue.
// Tiles loaded directly from fp16-staged g_embh (uint4 = 8 halfs per lane).
// Warp w owns output rows [16w, 16w+16) x 128 cols: d[16][4] fp32 fragments.
// ---------------------------------------------------------------------------
__device__ __forceinline__ void pairwise_body(char* smraw, int bid) {
    __half* Ahi = reinterpret_cast<__half*>(smraw);
    __half* Bhi = Ahi + 128 * TS;
    __shared__ int   labA[128], labB[128];
    __shared__ float sqA[128], sqB[128];
    __shared__ float s_cp[8][128], s_cn[8][128];

    // Triangular block decode: by <= bx
    float tf = sqrtf(8.0f * (float)bid + 1.0f);
    int bx = (int)((tf - 1.0f) * 0.5f);
    while ((bx + 1) * (bx + 2) / 2 <= bid) bx++;
    while (bx * (bx + 1) / 2 > bid) bx--;
    int by = bid - bx * (bx + 1) / 2;
    const bool diag = (by == bx);

    const int tid  = threadIdx.x;
    const int wid  = tid >> 5;
    const int lane = tid & 31;
    const int g    = lane >> 2;      // fragment group 0-7
    const int t    = lane & 3;       // thread-in-group 0-3
    const int i0   = by * 128;
    const int j0   = bx * 128;

    // Load fp16 tiles: each row = 128 halfs = 16 uint4; 2048 uint4 per tile.
    // 256 threads x 8 iters; smem row base row*TS*2 = row*272 (16B-aligned).
    const uint4* eh = reinterpret_cast<const uint4*>(g_embh);
    #pragma unroll
    for (int f = tid; f < 128 * 16; f += 256) {
        int row = f >> 4, c16 = f & 15;
        uint4 va = eh[(i0 + row) * 16 + c16];
        uint4 vb = eh[(j0 + row) * 16 + c16];
        *reinterpret_cast<uint4*>(Ahi + row * TS + c16 * 8) = va;
        *reinterpret_cast<uint4*>(Bhi + row * TS + c16 * 8) = vb;
    }
    if (tid < 128) {
        labA[tid] = g_lab[i0 + tid];
        labB[tid] = g_lab[j0 + tid];
        sqA[tid]  = g_sq[i0 + tid];
        sqB[tid]  = g_sq[j0 + tid];
    }
    __syncthreads();

    float d[16][4];
    #pragma unroll
    for (int nb = 0; nb < 16; nb++)
        #pragma unroll
        for (int e = 0; e < 4; e++) d[nb][e] = 0.0f;

    const int r0 = wid * 16;

    #pragma unroll 2
    for (int s = 0; s < 8; s++) {
        int k0 = 16 * s;
        uint32_t a0 = lds_u32(Ahi, r0 + g,     k0 + 2 * t);
        uint32_t a1 = lds_u32(Ahi, r0 + g + 8, k0 + 2 * t);
        uint32_t a2 = lds_u32(Ahi, r0 + g,     k0 + 8 + 2 * t);
        uint32_t a3 = lds_u32(Ahi, r0 + g + 8, k0 + 8 + 2 * t);
        #pragma unroll
        for (int nb = 0; nb < 16; nb++) {
            uint32_t b0 = lds_u32(Bhi, 8 * nb + g, k0 + 2 * t);
            uint32_t b1 = lds_u32(Bhi, 8 * nb + g, k0 + 8 + 2 * t);
            mma16816(d[nb], a0, a1, a2, a3, b0, b1);
        }
    }

    // Epilogue on fragment layout: thread (g,t) holds rows {r0+g, r0+g+8},
    // cols {8nb+2t, 8nb+2t+1}.
    const float INF = __int_as_float(0x7f800000);
    int   la0 = labA[r0 + g], la1 = labA[r0 + g + 8];
    float si0 = sqA[r0 + g],  si1 = sqA[r0 + g + 8];
    float rp0 = 0.0f, rn0 = INF, rp1 = 0.0f, rn1 = INF;

    #pragma unroll
    for (int nb = 0; nb < 16; nb++) {
        int   jc  = 8 * nb + 2 * t;
        int   lj0 = labB[jc], lj1 = labB[jc + 1];
        float sj0 = sqB[jc],  sj1 = sqB[jc + 1];
        float e00 = fmaxf(si0 + sj0 - 2.0f * d[nb][0], 0.0f);
        float e01 = fmaxf(si0 + sj1 - 2.0f * d[nb][1], 0.0f);
        float e10 = fmaxf(si1 + sj0 - 2.0f * d[nb][2], 0.0f);
        float e11 = fmaxf(si1 + sj1 - 2.0f * d[nb][3], 0.0f);

        // Row-side
        if (lj0 == la0) rp0 = fmaxf(rp0, e00); else rn0 = fminf(rn0, e00);
        if (lj1 == la0) rp0 = fmaxf(rp0, e01); else rn0 = fminf(rn0, e01);
        if (lj0 == la1) rp1 = fmaxf(rp1, e10); else rn1 = fminf(rn1, e10);
        if (lj1 == la1) rp1 = fmaxf(rp1, e11); else rn1 = fminf(rn1, e11);

        // Col-side (off-diagonal blocks only)
        if (!diag) {
            float cp0 = 0.0f, cn0 = INF, cp1 = 0.0f, cn1 = INF;
            if (lj0 == la0) cp0 = e00;             else cn0 = e00;
            if (lj0 == la1) cp0 = fmaxf(cp0, e10); else cn0 = fminf(cn0, e10);
            if (lj1 == la0) cp1 = e01;             else cn1 = e01;
            if (lj1 == la1) cp1 = fmaxf(cp1, e11); else cn1 = fminf(cn1, e11);
            #pragma unroll
            for (int m = 4; m <= 16; m <<= 1) {
                cp0 = fmaxf(cp0, __shfl_xor_sync(0xffffffffu, cp0, m));
                cn0 = fminf(cn0, __shfl_xor_sync(0xffffffffu, cn0, m));
                cp1 = fmaxf(cp1, __shfl_xor_sync(0xffffffffu, cp1, m));
                cn1 = fminf(cn1, __shfl_xor_sync(0xffffffffu, cn1, m));
            }
            if (g == 0) {
                s_cp[wid][jc]     = cp0;
                s_cp[wid][jc + 1] = cp1;
                s_cn[wid][jc]     = cn0;
                s_cn[wid][jc + 1] = cn1;
            }
        }
    }

    // Row combine across t + atomics
    #pragma unroll
    for (int m = 1; m <= 2; m <<= 1) {
        rp0 = fmaxf(rp0, __shfl_xor_sync(0xffffffffu, rp0, m));
        rn0 = fminf(rn0, __shfl_xor_sync(0xffffffffu, rn0, m));
        rp1 = fmaxf(rp1, __shfl_xor_sync(0xffffffffu, rp1, m));
        rn1 = fminf(rn1, __shfl_xor_sync(0xffffffffu, rn1, m));
    }
    if (t == 0) {
        atomicMax(&g_maxbits[i0 + r0 + g],     __float_as_int(rp0));
        atomicMin(&g_minbits[i0 + r0 + g],     __float_as_int(rn0));
        atomicMax(&g_maxbits[i0 + r0 + g + 8], __float_as_int(rp1));
        atomicMin(&g_minbits[i0 + r0 + g + 8], __float_as_int(rn1));
    }

    if (!diag) {
        __syncthreads();
        if (tid < 128) {
            float p = s_cp[0][tid], n = s_cn[0][tid];
            #pragma unroll
            for (int w = 1; w < 8; w++) {
                p = fmaxf(p, s_cp[w][tid]);
                n = fminf(n, s_cn[w][tid]);
            }
            atomicMax(&g_maxbits[j0 + tid], __float_as_int(p));
            atomicMin(&g_minbits[j0 + tid], __float_as_int(n));
        }
    }
}

// ---------------------------------------------------------------------------
// CE body (exact R6 version).
// ---------------------------------------------------------------------------
__device__ __forceinline__ void ce_body(float* sm, const float* __restrict__ emb,
                                        const float* __restrict__ w,
                                        const float* __restrict__ bias, int bid) {
    float* w_s = sm;                        // [100][133]
    float* e_s = sm + C * 133;              // [16][129]
    float* lg  = e_s + CE_ROWS * 129;       // [16][100]

    int tid = threadIdx.x;
    int r0  = bid * CE_ROWS;

    for (int f = tid; f < C * K; f += 256) {
        int c = f >> 7, k = f & 127;
        w_s[c * 133 + k] = w[f];
    }
    for (int f = tid; f < CE_ROWS * K; f += 256) {
        int r = f >> 7, k = f & 127;
        e_s[r * 129 + k] = emb[(r0 + r) * K + k];
    }
    __syncthreads();

    int grp = tid >> 7;
    int c   = tid & 127;
    if (c < C) {
        float accv[8];
        float bv = bias[c];
        #pragma unroll
        for (int r = 0; r < 8; r++) accv[r] = bv;
        for (int k = 0; k < K; k++) {
            float wv = w_s[c * 133 + k];
            #pragma unroll
            for (int r = 0; r < 8; r++)
                accv[r] = fmaf(wv, e_s[(grp * 8 + r) * 129 + k], accv[r]);
        }
        #pragma unroll
        for (int r = 0; r < 8; r++) lg[(grp * 8 + r) * C + c] = accv[r];
    }
    __syncthreads();

    if (tid < CE_ROWS) {
        int   lab = g_lab[r0 + tid];
        float m = -1e30f;
        for (int cc = 0; cc < C; cc++) m = fmaxf(m, lg[tid * C + cc]);
        float s = 0.0f;
        for (int cc = 0; cc < C; cc++) s += expf(lg[tid * C + cc] - m);
        g_ce[r0 + tid] = m + logf(s) - lg[tid * C + lab];
    }
}

// Fused kernel — no tail; 2 CTAs/SM for phase overlap.
__global__ void __launch_bounds__(256, 2)
fused_kernel(const float* __restrict__ emb, const float* __restrict__ w,
             const float* __restrict__ bias) {
    extern __shared__ char smraw[];
    if (blockIdx.x < PW_BLOCKS)
        pairwise_body(smraw, blockIdx.x);
    else
        ce_body(reinterpret_cast<float*>(smraw), emb, w, bias, blockIdx.x - PW_BLOCKS);
}

// ---------------------------------------------------------------------------
// Single reduce kernel (R9 version).
// ---------------------------------------------------------------------------
__global__ void reduce_kernel(float* __restrict__ out) {
    __shared__ float    s1[256], s2[256];
    __shared__ unsigned s_last;
    int t = threadIdx.x;
    int i = blockIdx.x * 256 + t;
    float mx = fmaxf(__int_as_float(g_maxbits[i]), 1e-12f);
    float mn = fmaxf(__int_as_float(g_minbits[i]), 1e-12f);
    s1[t] = fmaxf(sqrtf(mx) - sqrtf(mn) + MARGIN, 0.0f);
    s2[t] = g_ce[i];
    __syncthreads();
    #pragma unroll
    for (int s = 128; s > 0; s >>= 1) {
        if (t < s) { s1[t] += s1[t + s]; s2[t] += s2[t + s]; }
        __syncthreads();
    }
    if (t == 0) {
        g_part_tr[blockIdx.x] = s1[0];
        g_part_ce[blockIdx.x] = s2[0];
        __threadfence();
        s_last = (atomicAdd(&g_rdone, 1u) == 15u) ? 1u : 0u;
    }
    __syncthreads();
    if (s_last && t < 32) {
        float v = 0.0f;
        if (t < 16) v = __ldcg(&g_part_tr[t]) + __ldcg(&g_part_ce[t]);
        #pragma unroll
        for (int m = 8; m; m >>= 1) v += __shfl_xor_sync(0xffffffffu, v, m);
        if (t == 0) out[0] = v * (1.0f / (float)B);
    }
}

// ---------------------------------------------------------------------------
extern "C" void kernel_launch(void* const* d_in, const int* in_sizes, int n_in,
                              void* d_out, int out_size) {
    const float* emb    = (const float*)d_in[0];
    const int*   labels = (const int*)d_in[1];
    const float* fcw    = (const float*)d_in[2];
    const float* fcb    = (const float*)d_in[3];
    float*       out    = (float*)d_out;

    cudaFuncSetAttribute(fused_kernel,
                         cudaFuncAttributeMaxDynamicSharedMemorySize, PW_SMEM);

    void* p_rdone;
    cudaGetSymbolAddress(&p_rdone, g_rdone);
    cudaMemsetAsync(p_rdone, 0x00, sizeof(unsigned));

    prep_kernel<<<B / 64, 256>>>(emb, labels);
    fused_kernel<<<PW_BLOCKS + CE_BLOCKS, 256, PW_SMEM>>>(emb, fcw, fcb);
    reduce_kernel<<<16, 256>>>(out);
}